// round 16
// baseline (speedup 1.0000x reference)
#include <cuda_runtime.h>
#include <cstdint>

#define NBATCH 8
#define NTOT   32768
#define KDIM   128
#define NCH    37
#define TILE_N 64
#define CHUNK_TILES 14          // 37*14*64 = 33152 >= 32768; last chunk has 8 tiles
#define JACOBI_ITERS 8
#define THREADS 256
#define ROWB   272              // bytes per fp16 row: 128 f16 (256B) + 16 pad

// ---------------- global scratch (fully rewritten every replay) ----------------
__device__ float g_scr[NCH][NBATCH][KDIM][KDIM];  // split-K partials (LL quadrant unwritten/unread)
__device__ float g_msr[NCH][NBATCH][KDIM];        // rhs partials
__device__ float g_sa[NBATCH][KDIM][KDIM];
__device__ float g_mred[NBATCH][KDIM];

// ---------------- smem layout for gram kernel (dynamic) ----------------
#define SM_STAGE 0                     // [2][64][128] f32 = 65536
#define SM_H     65536                 // 64 * 272 = 17408
#define SM_MSK   82944                 // [2][64] f32
#define SM_DAT   83456                 // [2][64] f32
#define SM_MRED  83968                 // [128] f32
#define SMEM_TOTAL 84480

// ---------------- helpers ----------------
__device__ __forceinline__ uint32_t smem_u32(const void* p) {
    uint32_t a;
    asm("{ .reg .u64 t; cvta.to.shared.u64 t, %1; cvt.u32.u64 %0, t; }"
        : "=r"(a) : "l"(p));
    return a;
}
__device__ __forceinline__ void cp16(void* s, const void* g) {
    uint32_t a = smem_u32(s);
    asm volatile("cp.async.cg.shared.global [%0], [%1], 16;" :: "r"(a), "l"(g));
}
#define CP_COMMIT() asm volatile("cp.async.commit_group;" ::: "memory")
#define CP_WAIT(n)  asm volatile("cp.async.wait_group %0;" :: "n"(n) : "memory")

__device__ __forceinline__ void ldsm4t(uint32_t* r, uint32_t addr) {
    asm volatile("ldmatrix.sync.aligned.m8n8.x4.trans.shared.b16 {%0,%1,%2,%3}, [%4];"
                 : "=r"(r[0]), "=r"(r[1]), "=r"(r[2]), "=r"(r[3]) : "r"(addr));
}
__device__ __forceinline__ void mma_f16(float* d, const uint32_t* a, const uint32_t* b) {
    asm volatile(
        "mma.sync.aligned.m16n8k16.row.col.f32.f16.f16.f32 "
        "{%0,%1,%2,%3}, {%4,%5,%6,%7}, {%8,%9}, {%0,%1,%2,%3};"
        : "+f"(d[0]), "+f"(d[1]), "+f"(d[2]), "+f"(d[3])
        : "r"(a[0]), "r"(a[1]), "r"(a[2]), "r"(a[3]), "r"(b[0]), "r"(b[1]));
}
__device__ __forceinline__ uint32_t pack_h2(float lo, float hi) {
    uint32_t d;
    asm("cvt.rn.f16x2.f32 %0, %1, %2;" : "=r"(d) : "f"(hi), "f"(lo));
    return d;
}

// ---------------- kernel 1: split-K gram (R11/R15 code + anti-phase stagger) ----------------
__global__ void __launch_bounds__(THREADS, 2)
gram_kernel(const float* __restrict__ data, const float* __restrict__ mask,
            const float* __restrict__ mult) {
    extern __shared__ char smem[];
    const uint32_t smb = smem_u32(smem);
    const int tid = threadIdx.x;
    const int wid = tid >> 5;
    const int lane = tid & 31;
    const int chunk = blockIdx.x;
    const int b = blockIdx.y;
    const int n_start = chunk * (CHUNK_TILES * TILE_N);
    const int T = min(CHUNK_TILES, (NTOT - n_start) / TILE_N);

    float* stage = (float*)(smem + SM_STAGE);
    float* msk   = (float*)(smem + SM_MSK);
    float* dat   = (float*)(smem + SM_DAT);
    float* mred  = (float*)(smem + SM_MRED);
    const float* maskb = mask + (size_t)b * NTOT;
    const float* datab = data + (size_t)b * NTOT;

    if (tid < KDIM) mred[tid] = 0.f;

    auto prefetch = [&](int tt) {
        const int sb = tt & 1;
        const float* src = mult + (size_t)(n_start + tt * TILE_N) * KDIM;
        float* dst = stage + sb * (TILE_N * KDIM);
        #pragma unroll
        for (int s = 0; s < 8; ++s) {
            const int seg = tid + s * THREADS;         // 0..2047 16B segments
            cp16(dst + seg * 4, src + seg * 4);
        }
        if (tid < 16)      cp16(&msk[sb * 64 + tid * 4],        maskb + n_start + tt * 64 + tid * 4);
        else if (tid < 32) cp16(&dat[sb * 64 + (tid - 16) * 4], datab + n_start + tt * 64 + (tid - 16) * 4);
        CP_COMMIT();
    };

    prefetch(0);

    // ---- anti-phase stagger: classic placement puts bid and bid+148 on the same
    // SM; with grid (37, 8) those are (chunk, b) and (chunk, b+4). Delay the
    // b>=4 partner ~400 cyc so its convert phase overlaps the peer's MMA phase.
    if (b >= 4) {
        float z = (float)tid;
        #pragma unroll
        for (int q = 0; q < 96; ++q) z = fmaf(z, 1.0000001f, 1e-30f);
        if (z == 12345.678f) mred[0] = z;   // never true; defeats DCE
    }

    // conversion mapping: thread owns 4 consecutive k (float4), 8 rows (its warp's)
    const int kq = lane * 4;
    float macc[4] = {0.f, 0.f, 0.f, 0.f};

    // warp output-tile assignment (upper-triangle coverage, SMSP-balanced)
    const int i0 = (wid >> 1) * 32;
    const int j0 = (wid < 4) ? (wid & 1) * 64 : 96 - (wid & 1) * 32;
    const int ngw = (wid < 4) ? 4 : 2;

    // ldmatrix lane addressing (validated rounds 3-15)
    const int grp = lane >> 3, r = lane & 7;
    const uint32_t a_off = (uint32_t)(((grp & 2) ? 8 : 0) + r) * ROWB + (uint32_t)((grp & 1) ? 8 : 0) * 2;
    const uint32_t b_off = (uint32_t)(((grp & 1) ? 8 : 0) + r) * ROWB + (uint32_t)((grp & 2) ? 8 : 0) * 2;

    float acc[2][4][2][4];
    #pragma unroll
    for (int mt = 0; mt < 2; ++mt)
        #pragma unroll
        for (int g = 0; g < 4; ++g)
            #pragma unroll
            for (int nt = 0; nt < 2; ++nt)
                #pragma unroll
                for (int q = 0; q < 4; ++q) acc[mt][g][nt][q] = 0.f;

    for (int t = 0; t < T; ++t) {
        const int sb = t & 1;
        if (t + 1 < T) { prefetch(t + 1); CP_WAIT(1); }
        else           { CP_WAIT(0); }
        __syncthreads();    // stage[sb] ready; H free (prev MMA done)

        // ---- convert fp32 -> fp16 (float4 per thread), fold rhs ----
        {
            const float* st = stage + sb * (TILE_N * KDIM);
            const float* mk = msk + sb * 64;
            const float* dd = dat + sb * 64;
            char* hp_base = smem + SM_H;
            #pragma unroll
            for (int i = 0; i < 8; ++i) {
                const int n = (wid << 3) + i;
                const float4 v = *(const float4*)&st[n * KDIM + kq];
                const float w = mk[n], d = dd[n];
                const float x0 = v.x * w, x1 = v.y * w;
                const float x2 = v.z * w, x3 = v.w * w;
                macc[0] = fmaf(x0, d, macc[0]);
                macc[1] = fmaf(x1, d, macc[1]);
                macc[2] = fmaf(x2, d, macc[2]);
                macc[3] = fmaf(x3, d, macc[3]);
                *(uint2*)(hp_base + n * ROWB + kq * 2) =
                    make_uint2(pack_h2(x0, x1), pack_h2(x2, x3));
            }
        }
        __syncthreads();    // H visible to all warps

        // ---- MMAs: 4 k-steps of 16; diagonal blocks reuse A-fragments ----
        #pragma unroll
        for (int ks = 0; ks < 4; ++ks) {
            const uint32_t kofs = SM_H + (uint32_t)ks * 16 * ROWB;
            uint32_t af[2][4];
            ldsm4t(af[0], smb + kofs + a_off + (uint32_t)(i0) * 2);
            ldsm4t(af[1], smb + kofs + a_off + (uint32_t)(i0 + 16) * 2);
            #pragma unroll
            for (int g = 0; g < 4; ++g) {
                if (g < ngw) {
                    const int jblk = j0 + g * 16;
                    uint32_t bh[4];
                    if (jblk == i0) {            // B-frag = perm(A-frag) for diagonal block
                        bh[0] = af[0][0]; bh[1] = af[0][2];
                        bh[2] = af[0][1]; bh[3] = af[0][3];
                    } else if (jblk == i0 + 16) {
                        bh[0] = af[1][0]; bh[1] = af[1][2];
                        bh[2] = af[1][1]; bh[3] = af[1][3];
                    } else {
                        ldsm4t(bh, smb + kofs + b_off + (uint32_t)jblk * 2);
                    }
                    mma_f16(acc[0][g][0], af[0], bh + 0);
                    mma_f16(acc[0][g][1], af[0], bh + 2);
                    mma_f16(acc[1][g][0], af[1], bh + 0);
                    mma_f16(acc[1][g][1], af[1], bh + 2);
                }
            }
        }
    }

    // ---- rhs partial -> per-chunk STG ----
    atomicAdd(&mred[kq],     macc[0]);
    atomicAdd(&mred[kq + 1], macc[1]);
    atomicAdd(&mred[kq + 2], macc[2]);
    atomicAdd(&mred[kq + 3], macc[3]);
    __syncthreads();
    if (tid < KDIM) g_msr[chunk][b][tid] = mred[tid];

    // ---- epilogue: plain STG of computed tiles to scratch ----
    const int dg = lane >> 2, dt = (lane & 3) * 2;
    #pragma unroll
    for (int mt = 0; mt < 2; ++mt) {
        #pragma unroll
        for (int g = 0; g < 4; ++g) {
            if (g < ngw) {
                #pragma unroll
                for (int nt = 0; nt < 2; ++nt) {
                    const int i = i0 + mt * 16 + dg;
                    const int j = j0 + g * 16 + nt * 8 + dt;
                    *(float2*)&g_scr[chunk][b][i][j]     = make_float2(acc[mt][g][nt][0], acc[mt][g][nt][1]);
                    *(float2*)&g_scr[chunk][b][i + 8][j] = make_float2(acc[mt][g][nt][2], acc[mt][g][nt][3]);
                }
            }
        }
    }
}

// ---------------- kernel 2: reduce split-K partials + symmetrize + rhs ----------------
__global__ void reduce_kernel() {
    const int idx = blockIdx.x * 256 + threadIdx.x;
    const int PER4 = NBATCH * KDIM * KDIM / 4;    // 32768 float4 slots
    if (idx < PER4) {
        const int b = idx >> 12;
        const int rem = idx & 4095;
        const int i = rem >> 5;
        const int j = (rem & 31) * 4;
        if (i >= 64 && j < 64) return;            // filled by mirror
        float4 s = make_float4(0.f, 0.f, 0.f, 0.f);
        #pragma unroll
        for (int c = 0; c < NCH; ++c) {
            const float4 v = *(const float4*)&g_scr[c][b][i][j];
            s.x += v.x; s.y += v.y; s.z += v.z; s.w += v.w;
        }
        *(float4*)&g_sa[b][i][j] = s;
        if (i < 64 && j >= 64) {                  // mirror into skipped quadrant
            g_sa[b][j][i]     = s.x;
            g_sa[b][j + 1][i] = s.y;
            g_sa[b][j + 2][i] = s.z;
            g_sa[b][j + 3][i] = s.w;
        }
    } else if (idx < PER4 + NBATCH * KDIM) {
        const int r = idx - PER4;
        const float* p = (const float*)g_msr + r;
        float s = 0.f;
        #pragma unroll
        for (int c = 0; c < NCH; ++c) s += p[c * NBATCH * KDIM];
        ((float*)g_mred)[r] = s;
    }
}

// ---------------- kernel 3: Jacobi solve, split accumulator chains ----------------
__global__ void __launch_bounds__(256)
solve_kernel(const float* __restrict__ sigma_sq, float* __restrict__ out) {
    __shared__ float xs[2][KDIM];
    __shared__ float mv[KDIM];
    const int b = blockIdx.x;
    const int tid = threadIdx.x;            // 256
    const int i = tid >> 1;
    const int half = tid & 1;
    const int c0 = half * 64;
    const float sig = sigma_sq[0];

    float G[64];
    #pragma unroll
    for (int j4 = 0; j4 < 64; j4 += 4) {
        const float4 v = *(const float4*)&g_sa[b][i][c0 + j4];
        G[j4] = v.x; G[j4 + 1] = v.y; G[j4 + 2] = v.z; G[j4 + 3] = v.w;
    }
    if (half == (i >> 6)) G[i & 63] += sig;
    if (tid < KDIM) mv[tid] = g_mred[b][tid];

    float dval = (half == (i >> 6)) ? G[i & 63] : 0.f;
    dval += __shfl_xor_sync(0xffffffffu, dval, 1);
    const float di = 1.f / dval;
    __syncthreads();
    if (half == 0) xs[0][i] = mv[i] * di;
    __syncthreads();

    for (int it = 0; it < JACOBI_ITERS; ++it) {
        const float* xr = xs[it & 1];
        float* xw = xs[(it & 1) ^ 1];
        float s0 = 0.f, s1 = 0.f, s2 = 0.f, s3 = 0.f;
        #pragma unroll
        for (int j4 = 0; j4 < 16; j4 += 4) {
            const float4 v0 = *(const float4*)&xr[c0 + j4];
            const float4 v1 = *(const float4*)&xr[c0 + 16 + j4];
            const float4 v2 = *(const float4*)&xr[c0 + 32 + j4];
            const float4 v3 = *(const float4*)&xr[c0 + 48 + j4];
            s0 = fmaf(G[j4],          v0.x, s0);
            s0 = fmaf(G[j4 + 1],      v0.y, s0);
            s0 = fmaf(G[j4 + 2],      v0.z, s0);
            s0 = fmaf(G[j4 + 3],      v0.w, s0);
            s1 = fmaf(G[16 + j4],     v1.x, s1);
            s1 = fmaf(G[16 + j4 + 1], v1.y, s1);
            s1 = fmaf(G[16 + j4 + 2], v1.z, s1);
            s1 = fmaf(G[16 + j4 + 3], v1.w, s1);
            s2 = fmaf(G[32 + j4],     v2.x, s2);
            s2 = fmaf(G[32 + j4 + 1], v2.y, s2);
            s2 = fmaf(G[32 + j4 + 2], v2.z, s2);
            s2 = fmaf(G[32 + j4 + 3], v2.w, s2);
            s3 = fmaf(G[48 + j4],     v3.x, s3);
            s3 = fmaf(G[48 + j4 + 1], v3.y, s3);
            s3 = fmaf(G[48 + j4 + 2], v3.z, s3);
            s3 = fmaf(G[48 + j4 + 3], v3.w, s3);
        }
        float s = (s0 + s1) + (s2 + s3);
        s += __shfl_xor_sync(0xffffffffu, s, 1);
        if (half == 0) xw[i] = xr[i] + di * (mv[i] - s);
        __syncthreads();
    }
    if (half == 0) out[b * KDIM + i] = xs[0][i];   // even iter count -> buffer 0
}

// ---------------- launch ----------------
extern "C" void kernel_launch(void* const* d_in, const int* in_sizes, int n_in,
                              void* d_out, int out_size) {
    const float* data  = (const float*)d_in[0];
    const float* mask  = (const float*)d_in[1];
    const float* mult  = (const float*)d_in[2];
    const float* sigma = (const float*)d_in[3];
    float* out = (float*)d_out;

    cudaFuncSetAttribute(gram_kernel,
                         cudaFuncAttributeMaxDynamicSharedMemorySize, SMEM_TOTAL);

    dim3 grid(NCH, NBATCH);
    gram_kernel<<<grid, THREADS, SMEM_TOTAL>>>(data, mask, mult);

    const int total4 = NBATCH * KDIM * KDIM / 4 + NBATCH * KDIM;
    reduce_kernel<<<(total4 + 255) / 256, 256>>>();

    solve_kernel<<<NBATCH, 256>>>(sigma, out);
}